// round 6
// baseline (speedup 1.0000x reference)
#include <cuda_runtime.h>
#include <cuda_bf16.h>
#include <cstdint>

#define B_   8
#define N_   1024
#define H_   12
#define D_   64
#define DIM_ 768
#define BH_  (B_*H_)

// ---- split-bf16 scratch (device globals; no allocation in kernel_launch) ----
__device__ uint32_t g_q_hi[(size_t)BH_*N_*32], g_q_lo[(size_t)BH_*N_*32];
__device__ uint32_t g_k_hi[(size_t)BH_*N_*32], g_k_lo[(size_t)BH_*N_*32];
__device__ uint32_t g_v_hi[(size_t)BH_*N_*32], g_v_lo[(size_t)BH_*N_*32];
__device__ uint32_t g_x_hi[(size_t)B_*N_*384], g_x_lo[(size_t)B_*N_*384];
__device__ uint32_t g_w_hi[(size_t)DIM_*384],  g_w_lo[(size_t)DIM_*384];

// ---------------------------------------------------------------------------
// helpers
// ---------------------------------------------------------------------------
__device__ __forceinline__ uint32_t smem_u32(const void* p) {
    uint32_t a;
    asm("{ .reg .u64 t; cvta.to.shared.u64 t, %1; cvt.u32.u64 %0, t; }" : "=r"(a) : "l"(p));
    return a;
}
__device__ __forceinline__ void split2(float x0, float x1, uint32_t& hi, uint32_t& lo) {
    __nv_bfloat162 h = __floats2bfloat162_rn(x0, x1);
    float r0 = x0 - __bfloat162float(__low2bfloat16(h));
    float r1 = x1 - __bfloat162float(__high2bfloat16(h));
    __nv_bfloat162 l = __floats2bfloat162_rn(r0, r1);
    hi = *reinterpret_cast<uint32_t*>(&h);
    lo = *reinterpret_cast<uint32_t*>(&l);
}
// fast exp on FFMA/ALU pipes (no MUFU)
__device__ __forceinline__ float expf_fast(float x) {
    float t = fmaxf(x * 1.4426950408889634f, -126.0f);
    float n = floorf(t);
    float f = t - n;
    float p =            1.8775767e-3f;
    p = fmaf(p, f, 8.9893397e-3f);
    p = fmaf(p, f, 5.5826318e-2f);
    p = fmaf(p, f, 2.4015361e-1f);
    p = fmaf(p, f, 6.9315308e-1f);
    p = fmaf(p, f, 9.9999994e-1f);
    return __int_as_float(__float_as_int(p) + (((int)n) << 23));
}
__device__ __forceinline__ void ldsm4(uint32_t* r, uint32_t addr) {
    asm volatile("ldmatrix.sync.aligned.m8n8.x4.shared.b16 {%0,%1,%2,%3}, [%4];"
        : "=r"(r[0]), "=r"(r[1]), "=r"(r[2]), "=r"(r[3]) : "r"(addr));
}
__device__ __forceinline__ void ldsm4t(uint32_t* r, uint32_t addr) {
    asm volatile("ldmatrix.sync.aligned.m8n8.x4.trans.shared.b16 {%0,%1,%2,%3}, [%4];"
        : "=r"(r[0]), "=r"(r[1]), "=r"(r[2]), "=r"(r[3]) : "r"(addr));
}
__device__ __forceinline__ void mma_bf16(float* d, const uint32_t* a, uint32_t b0, uint32_t b1) {
    asm volatile(
        "mma.sync.aligned.m16n8k16.row.col.f32.bf16.bf16.f32 "
        "{%0,%1,%2,%3}, {%4,%5,%6,%7}, {%8,%9}, {%0,%1,%2,%3};"
        : "+f"(d[0]), "+f"(d[1]), "+f"(d[2]), "+f"(d[3])
        : "r"(a[0]), "r"(a[1]), "r"(a[2]), "r"(a[3]), "r"(b0), "r"(b1));
}
__device__ __forceinline__ void cpa16(uint32_t dst, const void* src) {
    asm volatile("cp.async.cg.shared.global [%0], [%1], 16;" :: "r"(dst), "l"(src) : "memory");
}
#define CP_COMMIT() asm volatile("cp.async.commit_group;" ::: "memory")
#define CP_WAIT1()  asm volatile("cp.async.wait_group 1;" ::: "memory")

// ---------------------------------------------------------------------------
// LayerNorm(q,k) + bf16 hi/lo split of q,k,v. One warp per (b,h,n).
// ---------------------------------------------------------------------------
__global__ __launch_bounds__(256) void ln_split_kernel(
    const float* __restrict__ QKV,
    const float* __restrict__ qw, const float* __restrict__ qb,
    const float* __restrict__ kw, const float* __restrict__ kb)
{
    int gw   = (blockIdx.x * blockDim.x + threadIdx.x) >> 5;
    int lane = threadIdx.x & 31;
    int n  = gw & (N_ - 1);
    int bh = gw >> 10;
    int h  = bh % H_;
    int b  = bh / H_;

    const float* base = QKV + ((size_t)(b * N_ + n)) * (3 * DIM_) + h * D_;
    float2 q = *(const float2*)(base + 2 * lane);
    float2 k = *(const float2*)(base + DIM_ + 2 * lane);
    float2 v = *(const float2*)(base + 2 * DIM_ + 2 * lane);

    float sq = q.x + q.y, sk = k.x + k.y;
    #pragma unroll
    for (int o = 16; o; o >>= 1) {
        sq += __shfl_xor_sync(0xffffffffu, sq, o);
        sk += __shfl_xor_sync(0xffffffffu, sk, o);
    }
    float muq = sq * (1.f / 64.f), muk = sk * (1.f / 64.f);
    float dq0 = q.x - muq, dq1 = q.y - muq;
    float dk0 = k.x - muk, dk1 = k.y - muk;
    float vq = dq0 * dq0 + dq1 * dq1;
    float vk = dk0 * dk0 + dk1 * dk1;
    #pragma unroll
    for (int o = 16; o; o >>= 1) {
        vq += __shfl_xor_sync(0xffffffffu, vq, o);
        vk += __shfl_xor_sync(0xffffffffu, vk, o);
    }
    float rq = rsqrtf(vq * (1.f / 64.f) + 1e-5f);
    float rk = rsqrtf(vk * (1.f / 64.f) + 1e-5f);
    const float scale = 0.125f;

    float q0 = (dq0 * rq * qw[2*lane]   + qb[2*lane])   * scale;
    float q1 = (dq1 * rq * qw[2*lane+1] + qb[2*lane+1]) * scale;
    float k0 =  dk0 * rk * kw[2*lane]   + kb[2*lane];
    float k1 =  dk1 * rk * kw[2*lane+1] + kb[2*lane+1];

    uint32_t hq, lq, hk, lk, hv, lv;
    split2(q0, q1, hq, lq);
    split2(k0, k1, hk, lk);
    split2(v.x, v.y, hv, lv);

    size_t ro = ((size_t)bh * N_ + n) * 32 + lane;
    g_q_hi[ro] = hq; g_q_lo[ro] = lq;
    g_k_hi[ro] = hk; g_k_lo[ro] = lk;
    g_v_hi[ro] = hv; g_v_lo[ro] = lv;
}

// ---------------------------------------------------------------------------
// Pre-split projection weights to bf16 hi/lo
// ---------------------------------------------------------------------------
__global__ __launch_bounds__(256) void w_split_kernel(const float* __restrict__ W)
{
    int i = blockIdx.x * 256 + threadIdx.x;
    float2 w = *(const float2*)(W + 2 * i);
    uint32_t hi, lo;
    split2(w.x, w.y, hi, lo);
    g_w_hi[i] = hi; g_w_lo[i] = lo;
}

// ---------------------------------------------------------------------------
// Flash attention v3: BM=128 (8 warps), fixed-base softmax (no running max),
// split-3 bf16 mma, P in registers, 2-stage cp.async K/V pipeline.
// ---------------------------------------------------------------------------
#define PITCH  144
#define KT_SZ  (64 * PITCH)       // 9216  (K/V tile)
#define QT_SZ  (128 * PITCH)      // 18432 (Q tile, 128 rows)
#define STG_SZ (4 * KT_SZ)        // 36864 per stage (KH,KL,VH,VL)
#define ATTN_SMEM (2 * STG_SZ)    // 73728; Q (2*QT_SZ = STG_SZ) overlays stage 1
#define OKH 0
#define OKL (1 * KT_SZ)
#define OVH (2 * KT_SZ)
#define OVL (3 * KT_SZ)
#define MBASE 10.0f               // |S| <= 8 post-layernorm => exp(S-10) in (0,1)

__global__ __launch_bounds__(256, 2) void attn_tc_kernel()
{
    extern __shared__ char sm[];
    uint32_t sb = smem_u32(sm);
    int tid = threadIdx.x, w = tid >> 5, lane = tid & 31;
    int qt = blockIdx.x, bh = blockIdx.y;
    int b = bh / H_, h = bh % H_;
    int i8 = lane & 7, sel = lane >> 3;
    int g = lane >> 2, t = lane & 3;

    int arow = ((sel & 1) << 3) + i8;
    int acol = (sel >> 1) << 3;
    int brow = ((sel >> 1) << 3) + i8;
    int bcol = (sel & 1) << 3;
    int vrow = ((sel & 1) << 3) + i8;
    int vcol = (sel >> 1) << 3;

    int fr = tid >> 3;              // 0..31
    int fc = tid & 7;
    size_t grow = (size_t)bh * N_;

    // ---- prologue: async K/V stage 0; Q into stage-1 area ----
    #pragma unroll
    for (int i = 0; i < 2; i++) {
        int r = fr + 32 * i;
        size_t gi = (grow + r) * 8 + fc;
        uint32_t d = sb + r * PITCH + fc * 16;
        cpa16(d + OKH, (const char*)g_k_hi + gi * 16);
        cpa16(d + OKL, (const char*)g_k_lo + gi * 16);
        cpa16(d + OVH, (const char*)g_v_hi + gi * 16);
        cpa16(d + OVL, (const char*)g_v_lo + gi * 16);
    }
    CP_COMMIT();
    #pragma unroll
    for (int i = 0; i < 4; i++) {
        int r = fr + 32 * i;
        size_t gi = (grow + qt * 128 + r) * 8 + fc;
        char* d = sm + STG_SZ + r * PITCH + fc * 16;
        *(uint4*)(d)         = ((const uint4*)g_q_hi)[gi];
        *(uint4*)(d + QT_SZ) = ((const uint4*)g_q_lo)[gi];
    }
    __syncthreads();

    // ---- preload Q fragments (warp w owns rows [16w,16w+16)) ----
    uint32_t qh[4][4], ql[4][4];
    #pragma unroll
    for (int kc = 0; kc < 4; kc++) {
        uint32_t ad = sb + STG_SZ + (16 * w + arow) * PITCH + (16 * kc + acol) * 2;
        ldsm4(qh[kc], ad);
        ldsm4(ql[kc], ad + QT_SZ);
    }
    __syncthreads();   // Q frags in regs before stage-1 is refilled

    float l0 = 0.f, l1 = 0.f;
    float o[8][4];
    #pragma unroll
    for (int s = 0; s < 8; s++)
        #pragma unroll
        for (int c = 0; c < 4; c++) o[s][c] = 0.f;

    for (int kt = 0; kt < N_ / 64; kt++) {
        uint32_t cb = sb + (uint32_t)(kt & 1) * STG_SZ;

        if (kt + 1 < N_ / 64) {
            uint32_t nb_ = sb + (uint32_t)((kt + 1) & 1) * STG_SZ;
            #pragma unroll
            for (int i = 0; i < 2; i++) {
                int r = fr + 32 * i;
                size_t gi = (grow + (kt + 1) * 64 + r) * 8 + fc;
                uint32_t d = nb_ + r * PITCH + fc * 16;
                cpa16(d + OKH, (const char*)g_k_hi + gi * 16);
                cpa16(d + OKL, (const char*)g_k_lo + gi * 16);
                cpa16(d + OVH, (const char*)g_v_hi + gi * 16);
                cpa16(d + OVL, (const char*)g_v_lo + gi * 16);
            }
        }
        CP_COMMIT();
        CP_WAIT1();
        __syncthreads();

        // ---- S = Q*K^T (split-3) ----
        float s[8][4];
        #pragma unroll
        for (int ss = 0; ss < 8; ss++)
            #pragma unroll
            for (int c = 0; c < 4; c++) s[ss][c] = 0.f;

        #pragma unroll
        for (int kc = 0; kc < 4; kc++) {
            #pragma unroll
            for (int nb = 0; nb < 4; nb++) {
                uint32_t kh4[4], kl4[4];
                uint32_t kd = cb + OKH + (nb * 16 + brow) * PITCH + (16 * kc + bcol) * 2;
                ldsm4(kh4, kd);
                ldsm4(kl4, kd + KT_SZ);
                mma_bf16(s[2*nb],   qh[kc], kh4[0], kh4[1]);
                mma_bf16(s[2*nb],   qh[kc], kl4[0], kl4[1]);
                mma_bf16(s[2*nb],   ql[kc], kh4[0], kh4[1]);
                mma_bf16(s[2*nb+1], qh[kc], kh4[2], kh4[3]);
                mma_bf16(s[2*nb+1], qh[kc], kl4[2], kl4[3]);
                mma_bf16(s[2*nb+1], ql[kc], kh4[2], kh4[3]);
            }
        }

        // ---- fixed-base softmax: p = exp(s - 10); no max, no rescale ----
        float r0 = 0.f, r1 = 0.f;
        #pragma unroll
        for (int ss = 0; ss < 8; ss++) {
            s[ss][0] = expf_fast(s[ss][0] - MBASE);
            s[ss][1] = expf_fast(s[ss][1] - MBASE);
            s[ss][2] = expf_fast(s[ss][2] - MBASE);
            s[ss][3] = expf_fast(s[ss][3] - MBASE);
            r0 += s[ss][0] + s[ss][1];
            r1 += s[ss][2] + s[ss][3];
        }
        r0 += __shfl_xor_sync(0xffffffffu, r0, 1);
        r0 += __shfl_xor_sync(0xffffffffu, r0, 2);
        r1 += __shfl_xor_sync(0xffffffffu, r1, 1);
        r1 += __shfl_xor_sync(0xffffffffu, r1, 2);
        l0 += r0;
        l1 += r1;

        // ---- O += P*V: P packed straight from S fragments ----
        #pragma unroll
        for (int kc = 0; kc < 4; kc++) {
            uint32_t ph[4], pl[4];
            split2(s[2*kc][0],   s[2*kc][1],   ph[0], pl[0]);
            split2(s[2*kc][2],   s[2*kc][3],   ph[1], pl[1]);
            split2(s[2*kc+1][0], s[2*kc+1][1], ph[2], pl[2]);
            split2(s[2*kc+1][2], s[2*kc+1][3], ph[3], pl[3]);
            #pragma unroll
            for (int nb = 0; nb < 4; nb++) {
                uint32_t vh4[4], vl4[4];
                uint32_t vd = cb + OVH + (16 * kc + vrow) * PITCH + (nb * 16 + vcol) * 2;
                ldsm4t(vh4, vd);
                ldsm4t(vl4, vd + KT_SZ);
                mma_bf16(o[2*nb],   ph, vh4[0], vh4[1]);
                mma_bf16(o[2*nb],   ph, vl4[0], vl4[1]);
                mma_bf16(o[2*nb],   pl, vh4[0], vh4[1]);
                mma_bf16(o[2*nb+1], ph, vh4[2], vh4[3]);
                mma_bf16(o[2*nb+1], ph, vl4[2], vl4[3]);
                mma_bf16(o[2*nb+1], pl, vh4[2], vh4[3]);
            }
        }
        __syncthreads();
    }

    // ---- epilogue ----
    float inv0 = 1.f / l0, inv1 = 1.f / l1;
    int n0 = qt * 128 + 16 * w + g;
    size_t ro0 = ((size_t)(b * N_ + n0)) * 384 + h * 32 + t;
    size_t ro1 = ro0 + (size_t)8 * 384;
    #pragma unroll
    for (int ss = 0; ss < 8; ss++) {
        uint32_t hi, lo;
        split2(o[ss][0] * inv0, o[ss][1] * inv0, hi, lo);
        g_x_hi[ro0 + ss * 4] = hi;
        g_x_lo[ro0 + ss * 4] = lo;
        split2(o[ss][2] * inv1, o[ss][3] * inv1, hi, lo);
        g_x_hi[ro1 + ss * 4] = hi;
        g_x_lo[ro1 + ss * 4] = lo;
    }
}

// ---------------------------------------------------------------------------
// Projection v3: 128m x 64n tile, 256 threads, 2-stage cp.async, split-3.
// ---------------------------------------------------------------------------
#define XT_SZ 18432                  // 128 rows * 144
#define WT_SZ 9216                   // 64 rows * 144
#define OXH 0
#define OXL (XT_SZ)
#define OWH (2 * XT_SZ)
#define OWL (2 * XT_SZ + WT_SZ)
#define PSTG (2 * XT_SZ + 2 * WT_SZ) // 55296
#define PROJ_SMEM (2 * PSTG)         // 110592

__global__ __launch_bounds__(256, 2) void proj_tc_kernel(
    const float* __restrict__ bias, float* __restrict__ out)
{
    extern __shared__ char sm[];
    uint32_t sb = smem_u32(sm);
    int tid = threadIdx.x, w = tid >> 5, lane = tid & 31;
    int rt = blockIdx.x, ct = blockIdx.y;
    int i8 = lane & 7, sel = lane >> 3;
    int g = lane >> 2, t = lane & 3;

    int arow = ((sel & 1) << 3) + i8;
    int acol = (sel >> 1) << 3;
    int brow = ((sel >> 1) << 3) + i8;
    int bcol = (sel & 1) << 3;

    int fr = tid >> 3, fc = tid & 7;

    auto fill = [&](int kc, uint32_t buf) {
        #pragma unroll
        for (int i = 0; i < 4; i++) {
            int r = fr + 32 * i;
            size_t xi = ((size_t)(rt * 128 + r)) * 96 + kc * 8 + fc;
            uint32_t d = buf + r * PITCH + fc * 16;
            cpa16(d + OXH, (const char*)g_x_hi + xi * 16);
            cpa16(d + OXL, (const char*)g_x_lo + xi * 16);
        }
        #pragma unroll
        for (int i = 0; i < 2; i++) {
            int r = fr + 32 * i;
            size_t wi = ((size_t)(ct * 64 + r)) * 96 + kc * 8 + fc;
            uint32_t d = buf + r * PITCH + fc * 16;
            cpa16(d + OWH, (const char*)g_w_hi + wi * 16);
            cpa16(d + OWL, (const char*)g_w_lo + wi * 16);
        }
    };

    float acc[8][4];
    #pragma unroll
    for (int s = 0; s < 8; s++)
        #pragma unroll
        for (int c = 0; c < 4; c++) acc[s][c] = 0.f;

    fill(0, sb);
    CP_COMMIT();

    for (int kc = 0; kc < 12; kc++) {
        uint32_t cb = sb + (uint32_t)(kc & 1) * PSTG;
        if (kc + 1 < 12) fill(kc + 1, sb + (uint32_t)((kc + 1) & 1) * PSTG);
        CP_COMMIT();
        CP_WAIT1();
        __syncthreads();

        #pragma unroll
        for (int k2 = 0; k2 < 4; k2++) {
            uint32_t ah4[4], al4[4];
            uint32_t ad = cb + OXH + (16 * w + arow) * PITCH + (16 * k2 + acol) * 2;
            ldsm4(ah4, ad);
            ldsm4(al4, ad + XT_SZ);
            #pragma unroll
            for (int nb = 0; nb < 4; nb++) {
                uint32_t wh4[4], wl4[4];
                uint32_t wd = cb + OWH + (nb * 16 + brow) * PITCH + (16 * k2 + bcol) * 2;
                ldsm4(wh4, wd);
                ldsm4(wl4, wd + WT_SZ);
                mma_bf16(acc[2*nb],   ah4, wh4[0], wh4[1]);
                mma_bf16(acc[2*nb],   ah4, wl4[0], wl4[1]);
                mma_bf16(acc[2*nb],   al4, wh4[0], wh4[1]);
                mma_bf16(acc[2*nb+1], ah4, wh4[2], wh4[3]);
                mma_bf16(acc[2*nb+1], ah4, wl4[2], wl4[3]);
                mma_bf16(acc[2*nb+1], al4, wh4[2], wh4[3]);
            }
        }
        __syncthreads();
    }

    int row = rt * 128 + 16 * w + g;
    #pragma unroll
    for (int ss = 0; ss < 8; ss++) {
        int col = ct * 64 + 8 * ss + 2 * t;
        float2 bv = *(const float2*)(bias + col);
        *(float2*)(out + (size_t)row * DIM_ + col) =
            make_float2(acc[ss][0] + bv.x, acc[ss][1] + bv.y);
        *(float2*)(out + (size_t)(row + 8) * DIM_ + col) =
            make_float2(acc[ss][2] + bv.x, acc[ss][3] + bv.y);
    }
}

// ---------------------------------------------------------------------------
extern "C" void kernel_launch(void* const* d_in, const int* in_sizes, int n_in,
                              void* d_out, int out_size)
{
    const float* QKV  = (const float*)d_in[0];
    const float* qw   = (const float*)d_in[1];
    const float* qb   = (const float*)d_in[2];
    const float* kw   = (const float*)d_in[3];
    const float* kb   = (const float*)d_in[4];
    const float* W    = (const float*)d_in[5];
    const float* bias = (const float*)d_in[6];
    float* out = (float*)d_out;

    cudaFuncSetAttribute(attn_tc_kernel,
                         cudaFuncAttributeMaxDynamicSharedMemorySize, ATTN_SMEM);
    cudaFuncSetAttribute(proj_tc_kernel,
                         cudaFuncAttributeMaxDynamicSharedMemorySize, PROJ_SMEM);

    ln_split_kernel<<<(BH_ * N_) / 8, 256>>>(QKV, qw, qb, kw, kb);
    w_split_kernel<<<(DIM_ * DIM_ / 2) / 256, 256>>>(W);
    attn_tc_kernel<<<dim3(N_ / 128, BH_), 256, ATTN_SMEM>>>();
    proj_tc_kernel<<<dim3((B_ * N_) / 128, DIM_ / 64), 256, PROJ_SMEM>>>(bias, out);
}

// round 7
// speedup vs baseline: 1.6597x; 1.6597x over previous
#include <cuda_runtime.h>
#include <cuda_bf16.h>
#include <cstdint>

#define B_   8
#define N_   1024
#define H_   12
#define D_   64
#define DIM_ 768
#define BH_  (B_*H_)

// ---- split-bf16 scratch (device globals; no allocation in kernel_launch) ----
__device__ uint32_t g_q_hi[(size_t)BH_*N_*32], g_q_lo[(size_t)BH_*N_*32];
__device__ uint32_t g_k_hi[(size_t)BH_*N_*32], g_k_lo[(size_t)BH_*N_*32];
__device__ uint32_t g_v_hi[(size_t)BH_*N_*32], g_v_lo[(size_t)BH_*N_*32];
__device__ uint32_t g_x_hi[(size_t)B_*N_*384], g_x_lo[(size_t)B_*N_*384];
__device__ uint32_t g_w_hi[(size_t)DIM_*384],  g_w_lo[(size_t)DIM_*384];

// ---------------------------------------------------------------------------
// helpers
// ---------------------------------------------------------------------------
__device__ __forceinline__ uint32_t smem_u32(const void* p) {
    uint32_t a;
    asm("{ .reg .u64 t; cvta.to.shared.u64 t, %1; cvt.u32.u64 %0, t; }" : "=r"(a) : "l"(p));
    return a;
}
__device__ __forceinline__ void split2(float x0, float x1, uint32_t& hi, uint32_t& lo) {
    __nv_bfloat162 h = __floats2bfloat162_rn(x0, x1);
    float r0 = x0 - __bfloat162float(__low2bfloat16(h));
    float r1 = x1 - __bfloat162float(__high2bfloat16(h));
    __nv_bfloat162 l = __floats2bfloat162_rn(r0, r1);
    hi = *reinterpret_cast<uint32_t*>(&h);
    lo = *reinterpret_cast<uint32_t*>(&l);
}
// fast exp on FFMA/ALU pipes (no MUFU)
__device__ __forceinline__ float expf_fast(float x) {
    float t = fmaxf(x * 1.4426950408889634f, -126.0f);
    float n = floorf(t);
    float f = t - n;
    float p =            1.8775767e-3f;
    p = fmaf(p, f, 8.9893397e-3f);
    p = fmaf(p, f, 5.5826318e-2f);
    p = fmaf(p, f, 2.4015361e-1f);
    p = fmaf(p, f, 6.9315308e-1f);
    p = fmaf(p, f, 9.9999994e-1f);
    return __int_as_float(__float_as_int(p) + (((int)n) << 23));
}
__device__ __forceinline__ void ldsm4(uint32_t* r, uint32_t addr) {
    asm volatile("ldmatrix.sync.aligned.m8n8.x4.shared.b16 {%0,%1,%2,%3}, [%4];"
        : "=r"(r[0]), "=r"(r[1]), "=r"(r[2]), "=r"(r[3]) : "r"(addr));
}
__device__ __forceinline__ void ldsm4t(uint32_t* r, uint32_t addr) {
    asm volatile("ldmatrix.sync.aligned.m8n8.x4.trans.shared.b16 {%0,%1,%2,%3}, [%4];"
        : "=r"(r[0]), "=r"(r[1]), "=r"(r[2]), "=r"(r[3]) : "r"(addr));
}
__device__ __forceinline__ void mma_bf16(float* d, const uint32_t* a, uint32_t b0, uint32_t b1) {
    asm volatile(
        "mma.sync.aligned.m16n8k16.row.col.f32.bf16.bf16.f32 "
        "{%0,%1,%2,%3}, {%4,%5,%6,%7}, {%8,%9}, {%0,%1,%2,%3};"
        : "+f"(d[0]), "+f"(d[1]), "+f"(d[2]), "+f"(d[3])
        : "r"(a[0]), "r"(a[1]), "r"(a[2]), "r"(a[3]), "r"(b0), "r"(b1));
}
__device__ __forceinline__ void cpa16(uint32_t dst, const void* src) {
    asm volatile("cp.async.cg.shared.global [%0], [%1], 16;" :: "r"(dst), "l"(src) : "memory");
}
#define CP_COMMIT() asm volatile("cp.async.commit_group;" ::: "memory")
#define CP_WAIT1()  asm volatile("cp.async.wait_group 1;" ::: "memory")

// ---------------------------------------------------------------------------
// LayerNorm(q,k) + bf16 hi/lo split of q,k,v. One warp per (b,h,n).
// ---------------------------------------------------------------------------
__global__ __launch_bounds__(256) void ln_split_kernel(
    const float* __restrict__ QKV,
    const float* __restrict__ qw, const float* __restrict__ qb,
    const float* __restrict__ kw, const float* __restrict__ kb)
{
    int gw   = (blockIdx.x * blockDim.x + threadIdx.x) >> 5;
    int lane = threadIdx.x & 31;
    int n  = gw & (N_ - 1);
    int bh = gw >> 10;
    int h  = bh % H_;
    int b  = bh / H_;

    const float* base = QKV + ((size_t)(b * N_ + n)) * (3 * DIM_) + h * D_;
    float2 q = *(const float2*)(base + 2 * lane);
    float2 k = *(const float2*)(base + DIM_ + 2 * lane);
    float2 v = *(const float2*)(base + 2 * DIM_ + 2 * lane);

    float sq = q.x + q.y, sk = k.x + k.y;
    #pragma unroll
    for (int o = 16; o; o >>= 1) {
        sq += __shfl_xor_sync(0xffffffffu, sq, o);
        sk += __shfl_xor_sync(0xffffffffu, sk, o);
    }
    float muq = sq * (1.f / 64.f), muk = sk * (1.f / 64.f);
    float dq0 = q.x - muq, dq1 = q.y - muq;
    float dk0 = k.x - muk, dk1 = k.y - muk;
    float vq = dq0 * dq0 + dq1 * dq1;
    float vk = dk0 * dk0 + dk1 * dk1;
    #pragma unroll
    for (int o = 16; o; o >>= 1) {
        vq += __shfl_xor_sync(0xffffffffu, vq, o);
        vk += __shfl_xor_sync(0xffffffffu, vk, o);
    }
    float rq = rsqrtf(vq * (1.f / 64.f) + 1e-5f);
    float rk = rsqrtf(vk * (1.f / 64.f) + 1e-5f);
    const float scale = 0.125f;

    float q0 = (dq0 * rq * qw[2*lane]   + qb[2*lane])   * scale;
    float q1 = (dq1 * rq * qw[2*lane+1] + qb[2*lane+1]) * scale;
    float k0 =  dk0 * rk * kw[2*lane]   + kb[2*lane];
    float k1 =  dk1 * rk * kw[2*lane+1] + kb[2*lane+1];

    uint32_t hq, lq, hk, lk, hv, lv;
    split2(q0, q1, hq, lq);
    split2(k0, k1, hk, lk);
    split2(v.x, v.y, hv, lv);

    size_t ro = ((size_t)bh * N_ + n) * 32 + lane;
    g_q_hi[ro] = hq; g_q_lo[ro] = lq;
    g_k_hi[ro] = hk; g_k_lo[ro] = lk;
    g_v_hi[ro] = hv; g_v_lo[ro] = lv;
}

// ---------------------------------------------------------------------------
// Pre-split projection weights to bf16 hi/lo
// ---------------------------------------------------------------------------
__global__ __launch_bounds__(256) void w_split_kernel(const float* __restrict__ W)
{
    int i = blockIdx.x * 256 + threadIdx.x;
    float2 w = *(const float2*)(W + 2 * i);
    uint32_t hi, lo;
    split2(w.x, w.y, hi, lo);
    g_w_hi[i] = hi; g_w_lo[i] = lo;
}

// ---------------------------------------------------------------------------
// Flash attention (R5 shape: BM=64, 128 threads, 3 CTAs/SM) +
// fixed-base softmax (no running max; exact by shift invariance, |S|<=8).
// ---------------------------------------------------------------------------
#define PITCH  144
#define T_SZ   (64 * PITCH)      // 9216
#define STG_SZ (4 * T_SZ)        // 36864 (KH,KL,VH,VL)
#define ATTN_SMEM (2 * STG_SZ)   // 73728; Q overlays stage 1 during prologue
#define OKH 0
#define OKL (1 * T_SZ)
#define OVH (2 * T_SZ)
#define OVL (3 * T_SZ)
#define MBASE 10.0f

__global__ __launch_bounds__(128, 3) void attn_tc_kernel()
{
    extern __shared__ char sm[];
    uint32_t sb = smem_u32(sm);
    int tid = threadIdx.x, w = tid >> 5, lane = tid & 31;
    int qt = blockIdx.x, bh = blockIdx.y;
    int b = bh / H_, h = bh % H_;
    int i8 = lane & 7, sel = lane >> 3;
    int g = lane >> 2, t = lane & 3;

    int arow = ((sel & 1) << 3) + i8;
    int acol = (sel >> 1) << 3;
    int brow = ((sel >> 1) << 3) + i8;
    int bcol = (sel & 1) << 3;
    int vrow = ((sel & 1) << 3) + i8;
    int vcol = (sel >> 1) << 3;

    int fr  = tid >> 3;
    int fc  = tid & 7;
    size_t grow = (size_t)bh * N_;

    // ---- prologue: async-fill K/V stage 0, fill Q into stage-1 area ----
    #pragma unroll
    for (int i = 0; i < 4; i++) {
        int r = fr + 16 * i;
        size_t gi = (grow + r) * 8 + fc;
        uint32_t d = sb + r * PITCH + fc * 16;
        cpa16(d + OKH, (const char*)g_k_hi + gi * 16);
        cpa16(d + OKL, (const char*)g_k_lo + gi * 16);
        cpa16(d + OVH, (const char*)g_v_hi + gi * 16);
        cpa16(d + OVL, (const char*)g_v_lo + gi * 16);
    }
    CP_COMMIT();
    #pragma unroll
    for (int i = 0; i < 4; i++) {
        int r = fr + 16 * i;
        size_t gi = (grow + qt * 64 + r) * 8 + fc;
        char* d = sm + STG_SZ + r * PITCH + fc * 16;
        *(uint4*)(d)        = ((const uint4*)g_q_hi)[gi];
        *(uint4*)(d + T_SZ) = ((const uint4*)g_q_lo)[gi];
    }
    __syncthreads();

    // ---- preload Q fragments ----
    uint32_t qh[4][4], ql[4][4];
    #pragma unroll
    for (int kc = 0; kc < 4; kc++) {
        uint32_t ad = sb + STG_SZ + (16 * w + arow) * PITCH + (16 * kc + acol) * 2;
        ldsm4(qh[kc], ad);
        ldsm4(ql[kc], ad + T_SZ);
    }
    __syncthreads();

    float l0 = 0.f, l1 = 0.f;
    float o[8][4];
    #pragma unroll
    for (int s = 0; s < 8; s++)
        #pragma unroll
        for (int c = 0; c < 4; c++) o[s][c] = 0.f;

    for (int kt = 0; kt < N_ / 64; kt++) {
        uint32_t cb = sb + (uint32_t)(kt & 1) * STG_SZ;

        if (kt + 1 < N_ / 64) {
            uint32_t nb_ = sb + (uint32_t)((kt + 1) & 1) * STG_SZ;
            #pragma unroll
            for (int i = 0; i < 4; i++) {
                int r = fr + 16 * i;
                size_t gi = (grow + (kt + 1) * 64 + r) * 8 + fc;
                uint32_t d = nb_ + r * PITCH + fc * 16;
                cpa16(d + OKH, (const char*)g_k_hi + gi * 16);
                cpa16(d + OKL, (const char*)g_k_lo + gi * 16);
                cpa16(d + OVH, (const char*)g_v_hi + gi * 16);
                cpa16(d + OVL, (const char*)g_v_lo + gi * 16);
            }
        }
        CP_COMMIT();
        CP_WAIT1();
        __syncthreads();

        // ---- S = Q*K^T (split-3) ----
        float s[8][4];
        #pragma unroll
        for (int ss = 0; ss < 8; ss++)
            #pragma unroll
            for (int c = 0; c < 4; c++) s[ss][c] = 0.f;

        #pragma unroll
        for (int kc = 0; kc < 4; kc++) {
            #pragma unroll
            for (int nb = 0; nb < 4; nb++) {
                uint32_t kh4[4], kl4[4];
                uint32_t kd = cb + OKH + (nb * 16 + brow) * PITCH + (16 * kc + bcol) * 2;
                ldsm4(kh4, kd);
                ldsm4(kl4, kd + T_SZ);
                mma_bf16(s[2*nb],   qh[kc], kh4[0], kh4[1]);
                mma_bf16(s[2*nb],   qh[kc], kl4[0], kl4[1]);
                mma_bf16(s[2*nb],   ql[kc], kh4[0], kh4[1]);
                mma_bf16(s[2*nb+1], qh[kc], kh4[2], kh4[3]);
                mma_bf16(s[2*nb+1], qh[kc], kl4[2], kl4[3]);
                mma_bf16(s[2*nb+1], ql[kc], kh4[2], kh4[3]);
            }
        }

        // ---- fixed-base softmax: p = exp(s - 10); no max, no rescale ----
        float r0 = 0.f, r1 = 0.f;
        #pragma unroll
        for (int ss = 0; ss < 8; ss++) {
            s[ss][0] = expf_fast(s[ss][0] - MBASE);
            s[ss][1] = expf_fast(s[ss][1] - MBASE);
            s[ss][2] = expf_fast(s[ss][2] - MBASE);
            s[ss][3] = expf_fast(s[ss][3] - MBASE);
            r0 += s[ss][0] + s[ss][1];
            r1 += s[ss][2] + s[ss][3];
        }
        r0 += __shfl_xor_sync(0xffffffffu, r0, 1);
        r0 += __shfl_xor_sync(0xffffffffu, r0, 2);
        r1 += __shfl_xor_sync(0xffffffffu, r1, 1);
        r1 += __shfl_xor_sync(0xffffffffu, r1, 2);
        l0 += r0;
        l1 += r1;

        // ---- O += P*V: P packed straight from S fragments ----
        #pragma unroll
        for (int kc = 0; kc < 4; kc++) {
            uint32_t ph[4], pl[4];
            split2(s[2*kc][0],   s[2*kc][1],   ph[0], pl[0]);
            split2(s[2*kc][2],   s[2*kc][3],   ph[1], pl[1]);
            split2(s[2*kc+1][0], s[2*kc+1][1], ph[2], pl[2]);
            split2(s[2*kc+1][2], s[2*kc+1][3], ph[3], pl[3]);
            #pragma unroll
            for (int nb = 0; nb < 4; nb++) {
                uint32_t vh4[4], vl4[4];
                uint32_t vd = cb + OVH + (16 * kc + vrow) * PITCH + (nb * 16 + vcol) * 2;
                ldsm4t(vh4, vd);
                ldsm4t(vl4, vd + T_SZ);
                mma_bf16(o[2*nb],   ph, vh4[0], vh4[1]);
                mma_bf16(o[2*nb],   ph, vl4[0], vl4[1]);
                mma_bf16(o[2*nb],   pl, vh4[0], vh4[1]);
                mma_bf16(o[2*nb+1], ph, vh4[2], vh4[3]);
                mma_bf16(o[2*nb+1], ph, vl4[2], vl4[3]);
                mma_bf16(o[2*nb+1], pl, vh4[2], vh4[3]);
            }
        }
        __syncthreads();
    }

    // ---- epilogue ----
    float inv0 = 1.f / l0, inv1 = 1.f / l1;
    int n0 = qt * 64 + 16 * w + g;
    size_t ro0 = ((size_t)(b * N_ + n0)) * 384 + h * 32 + t;
    size_t ro1 = ro0 + (size_t)8 * 384;
    #pragma unroll
    for (int ss = 0; ss < 8; ss++) {
        uint32_t hi, lo;
        split2(o[ss][0] * inv0, o[ss][1] * inv0, hi, lo);
        g_x_hi[ro0 + ss * 4] = hi;
        g_x_lo[ro0 + ss * 4] = lo;
        split2(o[ss][2] * inv1, o[ss][3] * inv1, hi, lo);
        g_x_hi[ro1 + ss * 4] = hi;
        g_x_lo[ro1 + ss * 4] = lo;
    }
}

// ---------------------------------------------------------------------------
// Projection (R5 shape): 64m x 64n, 128 threads, 2-stage cp.async, split-3.
// ---------------------------------------------------------------------------
#define OXH 0
#define OXL (1 * T_SZ)
#define OWH (2 * T_SZ)
#define OWL (3 * T_SZ)
#define PROJ_SMEM (2 * STG_SZ)

__global__ __launch_bounds__(128, 3) void proj_tc_kernel(
    const float* __restrict__ bias, float* __restrict__ out)
{
    extern __shared__ char sm[];
    uint32_t sb = smem_u32(sm);
    int tid = threadIdx.x, w = tid >> 5, lane = tid & 31;
    int rt = blockIdx.x, ct = blockIdx.y;
    int i8 = lane & 7, sel = lane >> 3;
    int g = lane >> 2, t = lane & 3;

    int arow = ((sel & 1) << 3) + i8;
    int acol = (sel >> 1) << 3;
    int brow = ((sel >> 1) << 3) + i8;
    int bcol = (sel & 1) << 3;

    int fr = tid >> 3, fc = tid & 7;

    auto fill = [&](int kc, uint32_t buf) {
        #pragma unroll
        for (int i = 0; i < 4; i++) {
            int r = fr + 16 * i;
            size_t xi = ((size_t)(rt * 64 + r)) * 96 + kc * 8 + fc;
            size_t wi = ((size_t)(ct * 64 + r)) * 96 + kc * 8 + fc;
            uint32_t d = buf + r * PITCH + fc * 16;
            cpa16(d + OXH, (const char*)g_x_hi + xi * 16);
            cpa16(d + OXL, (const char*)g_x_lo + xi * 16);
            cpa16(d + OWH, (const char*)g_w_hi + wi * 16);
            cpa16(d + OWL, (const char*)g_w_lo + wi * 16);
        }
    };

    float acc[8][4];
    #pragma unroll
    for (int s = 0; s < 8; s++)
        #pragma unroll
        for (int c = 0; c < 4; c++) acc[s][c] = 0.f;

    fill(0, sb);
    CP_COMMIT();

    for (int kc = 0; kc < 12; kc++) {
        uint32_t cb = sb + (uint32_t)(kc & 1) * STG_SZ;
        if (kc + 1 < 12) fill(kc + 1, sb + (uint32_t)((kc + 1) & 1) * STG_SZ);
        CP_COMMIT();
        CP_WAIT1();
        __syncthreads();

        #pragma unroll
        for (int k2 = 0; k2 < 4; k2++) {
            uint32_t ah4[4], al4[4];
            uint32_t ad = cb + OXH + (16 * w + arow) * PITCH + (16 * k2 + acol) * 2;
            ldsm4(ah4, ad);
            ldsm4(al4, ad + T_SZ);
            #pragma unroll
            for (int nb = 0; nb < 4; nb++) {
                uint32_t wh4[4], wl4[4];
                uint32_t wd = cb + OWH + (nb * 16 + brow) * PITCH + (16 * k2 + bcol) * 2;
                ldsm4(wh4, wd);
                ldsm4(wl4, wd + T_SZ);
                mma_bf16(acc[2*nb],   ah4, wh4[0], wh4[1]);
                mma_bf16(acc[2*nb],   ah4, wl4[0], wl4[1]);
                mma_bf16(acc[2*nb],   al4, wh4[0], wh4[1]);
                mma_bf16(acc[2*nb+1], ah4, wh4[2], wh4[3]);
                mma_bf16(acc[2*nb+1], ah4, wl4[2], wl4[3]);
                mma_bf16(acc[2*nb+1], al4, wh4[2], wh4[3]);
            }
        }
        __syncthreads();
    }

    int row = rt * 64 + 16 * w + g;
    #pragma unroll
    for (int ss = 0; ss < 8; ss++) {
        int col = ct * 64 + 8 * ss + 2 * t;
        float2 bv = *(const float2*)(bias + col);
        *(float2*)(out + (size_t)row * DIM_ + col) =
            make_float2(acc[ss][0] + bv.x, acc[ss][1] + bv.y);
        *(float2*)(out + (size_t)(row + 8) * DIM_ + col) =
            make_float2(acc[ss][2] + bv.x, acc[ss][3] + bv.y);
    }
}

// ---------------------------------------------------------------------------
extern "C" void kernel_launch(void* const* d_in, const int* in_sizes, int n_in,
                              void* d_out, int out_size)
{
    const float* QKV  = (const float*)d_in[0];
    const float* qw   = (const float*)d_in[1];
    const float* qb   = (const float*)d_in[2];
    const float* kw   = (const float*)d_in[3];
    const float* kb   = (const float*)d_in[4];
    const float* W    = (const float*)d_in[5];
    const float* bias = (const float*)d_in[6];
    float* out = (float*)d_out;

    cudaFuncSetAttribute(attn_tc_kernel,
                         cudaFuncAttributeMaxDynamicSharedMemorySize, ATTN_SMEM);
    cudaFuncSetAttribute(proj_tc_kernel,
                         cudaFuncAttributeMaxDynamicSharedMemorySize, PROJ_SMEM);

    ln_split_kernel<<<(BH_ * N_) / 8, 256>>>(QKV, qw, qb, kw, kb);
    w_split_kernel<<<(DIM_ * DIM_ / 2) / 256, 256>>>(W);
    attn_tc_kernel<<<dim3(N_ / 64, BH_), 128, ATTN_SMEM>>>();
    proj_tc_kernel<<<dim3((B_ * N_) / 64, DIM_ / 64), 128, PROJ_SMEM>>>(bias, out);
}